// round 4
// baseline (speedup 1.0000x reference)
#include <cuda_runtime.h>
#include <cuda_fp16.h>
#include <cstdint>

#define D_MODEL 2048
#define SEQ     1024
#define NHEADS  256
#define HDIM    8
#define OUT_ELEMS (SEQ*D_MODEL)            // 2097152

// ---------------- scratch (no allocations allowed) ----------------
__device__ float g_q[SEQ*D_MODEL];   // 8 MB
__device__ float g_y[SEQ*D_MODEL];   // 8 MB
__device__ float g_k[SEQ*HDIM];
__device__ float g_v[SEQ*HDIM];

static __device__ __forceinline__ unsigned f2tf(float x){
    unsigned r; asm("cvt.rna.tf32.f32 %0, %1;" : "=r"(r) : "f"(x)); return r;
}

#define MMA8(d, a, b) asm volatile( \
  "mma.sync.aligned.m16n8k8.row.col.f32.tf32.tf32.f32 " \
  "{%0,%1,%2,%3},{%4,%5,%6,%7},{%8,%9},{%0,%1,%2,%3};\n" \
  : "+f"(d[0]), "+f"(d[1]), "+f"(d[2]), "+f"(d[3]) \
  : "r"(a[0]),"r"(a[1]),"r"(a[2]),"r"(a[3]), "r"(b[0]),"r"(b[1]))

// ================= 3xTF32 GEMM: C = A[MxK] @ B[KxN] + bias ==================
// BM=128 BN=64 BK=16, 256 threads, warp grid 4x2, warp tile 32x32.
// Double-buffered smem, 2 CTAs/SM, grid=256 = one full wave at 148 SMs.
#define GBM 128
#define GBN 64
#define GBK 16
#define ASTR 20      // 16+4 pad
#define BSTR 72      // 64+8 pad
#define ASZ (GBM*ASTR)              // 2560 u32
#define BSZ (GBK*BSTR)              // 1152 u32
#define STAGE_U32 (2*ASZ + 2*BSZ)   // 7424 u32 per stage
#define GEMM_SMEM (2*STAGE_U32*4)   // 59392 B

__global__ __launch_bounds__(256, 2) void gemm3tf32(
    const float* __restrict__ A, const float* __restrict__ B,
    const float* __restrict__ bias, float* __restrict__ C,
    int M, int N, int K)
{
    extern __shared__ unsigned gsm[];
    const int tid = threadIdx.x;
    const int warp = tid >> 5, lane = tid & 31;
    const int wm = warp >> 1, wn = warp & 1;
    const int m0 = blockIdx.y * GBM, n0 = blockIdx.x * GBN;

    float acc[2][4][4];
    #pragma unroll
    for (int a = 0; a < 2; a++)
        #pragma unroll
        for (int b = 0; b < 4; b++)
            #pragma unroll
            for (int c = 0; c < 4; c++) acc[a][b][c] = 0.f;

    // A: 128x16 = 512 float4, 2/thread.  B: 16x64 = 256 float4, 1/thread.
    const int arow0 = (tid      ) >> 2, ac4_0 = (tid      ) & 3;
    const int arow1 = (tid + 256) >> 2, ac4_1 = (tid + 256) & 3;
    const int brow  = tid >> 4,  bc4 = tid & 15;

    float4 ar0, ar1, brv;
    const int KT = K / GBK;

    // prefetch tile 0
    ar0 = *(const float4*)(A + (size_t)(m0+arow0)*K + ac4_0*4);
    ar1 = *(const float4*)(A + (size_t)(m0+arow1)*K + ac4_1*4);
    brv = *(const float4*)(B + (size_t)brow*N + n0 + bc4*4);

    // stage tile 0 into stage 0
    {
        unsigned* Ah = gsm;            unsigned* Al = gsm + ASZ;
        unsigned* Bh = gsm + 2*ASZ;    unsigned* Bl = gsm + 2*ASZ + BSZ;
        float av0[4] = {ar0.x, ar0.y, ar0.z, ar0.w};
        float av1[4] = {ar1.x, ar1.y, ar1.z, ar1.w};
        float bv4[4] = {brv.x, brv.y, brv.z, brv.w};
        #pragma unroll
        for (int e = 0; e < 4; e++){
            unsigned hb = f2tf(av0[e]); float hf = __uint_as_float(hb);
            Ah[arow0*ASTR + ac4_0*4 + e] = hb;
            Al[arow0*ASTR + ac4_0*4 + e] = f2tf(av0[e] - hf);
            hb = f2tf(av1[e]); hf = __uint_as_float(hb);
            Ah[arow1*ASTR + ac4_1*4 + e] = hb;
            Al[arow1*ASTR + ac4_1*4 + e] = f2tf(av1[e] - hf);
            hb = f2tf(bv4[e]); hf = __uint_as_float(hb);
            Bh[brow*BSTR + bc4*4 + e] = hb;
            Bl[brow*BSTR + bc4*4 + e] = f2tf(bv4[e] - hf);
        }
    }
    __syncthreads();

    for (int kt = 0; kt < KT; ++kt){
        // issue next-tile global loads early (hidden under MMAs)
        if (kt + 1 < KT){
            int k0 = (kt+1)*GBK;
            ar0 = *(const float4*)(A + (size_t)(m0+arow0)*K + k0 + ac4_0*4);
            ar1 = *(const float4*)(A + (size_t)(m0+arow1)*K + k0 + ac4_1*4);
            brv = *(const float4*)(B + (size_t)(k0+brow)*N + n0 + bc4*4);
        }
        // compute on current stage
        {
            unsigned* base = gsm + (kt & 1)*STAGE_U32;
            unsigned* Ah = base;           unsigned* Al = base + ASZ;
            unsigned* Bh = base + 2*ASZ;   unsigned* Bl = base + 2*ASZ + BSZ;
            #pragma unroll
            for (int ks = 0; ks < 2; ++ks){
                unsigned ah[2][4], al2[2][4], bh[4][2], bl2[4][2];
                #pragma unroll
                for (int mt = 0; mt < 2; ++mt){
                    int r = wm*32 + mt*16 + (lane >> 2);
                    int c = ks*8 + (lane & 3);
                    ah[mt][0]=Ah[r*ASTR+c];      ah[mt][1]=Ah[(r+8)*ASTR+c];
                    ah[mt][2]=Ah[r*ASTR+c+4];    ah[mt][3]=Ah[(r+8)*ASTR+c+4];
                    al2[mt][0]=Al[r*ASTR+c];     al2[mt][1]=Al[(r+8)*ASTR+c];
                    al2[mt][2]=Al[r*ASTR+c+4];   al2[mt][3]=Al[(r+8)*ASTR+c+4];
                }
                #pragma unroll
                for (int nt = 0; nt < 4; ++nt){
                    int col = wn*32 + nt*8 + (lane >> 2);
                    int row = ks*8 + (lane & 3);
                    bh[nt][0]=Bh[row*BSTR+col];  bh[nt][1]=Bh[(row+4)*BSTR+col];
                    bl2[nt][0]=Bl[row*BSTR+col]; bl2[nt][1]=Bl[(row+4)*BSTR+col];
                }
                #pragma unroll
                for (int mt = 0; mt < 2; ++mt)
                    #pragma unroll
                    for (int nt = 0; nt < 4; ++nt){
                        MMA8(acc[mt][nt], ah[mt],  bh[nt]);
                        MMA8(acc[mt][nt], ah[mt],  bl2[nt]);
                        MMA8(acc[mt][nt], al2[mt], bh[nt]);
                    }
            }
        }
        // stage next tile into the other buffer
        if (kt + 1 < KT){
            unsigned* base = gsm + ((kt+1) & 1)*STAGE_U32;
            unsigned* Ah = base;           unsigned* Al = base + ASZ;
            unsigned* Bh = base + 2*ASZ;   unsigned* Bl = base + 2*ASZ + BSZ;
            float av0[4] = {ar0.x, ar0.y, ar0.z, ar0.w};
            float av1[4] = {ar1.x, ar1.y, ar1.z, ar1.w};
            float bv4[4] = {brv.x, brv.y, brv.z, brv.w};
            #pragma unroll
            for (int e = 0; e < 4; e++){
                unsigned hb = f2tf(av0[e]); float hf = __uint_as_float(hb);
                Ah[arow0*ASTR + ac4_0*4 + e] = hb;
                Al[arow0*ASTR + ac4_0*4 + e] = f2tf(av0[e] - hf);
                hb = f2tf(av1[e]); hf = __uint_as_float(hb);
                Ah[arow1*ASTR + ac4_1*4 + e] = hb;
                Al[arow1*ASTR + ac4_1*4 + e] = f2tf(av1[e] - hf);
                hb = f2tf(bv4[e]); hf = __uint_as_float(hb);
                Bh[brow*BSTR + bc4*4 + e] = hb;
                Bl[brow*BSTR + bc4*4 + e] = f2tf(bv4[e] - hf);
            }
        }
        __syncthreads();
    }

    #pragma unroll
    for (int mt = 0; mt < 2; ++mt){
        int r = m0 + wm*32 + mt*16 + (lane >> 2);
        #pragma unroll
        for (int nt = 0; nt < 4; ++nt){
            int cb = n0 + wn*32 + nt*8 + 2*(lane & 3);
            float b0 = bias[cb], b1 = bias[cb+1];
            float2 v0 = make_float2(acc[mt][nt][0]+b0, acc[mt][nt][1]+b1);
            float2 v1 = make_float2(acc[mt][nt][2]+b0, acc[mt][nt][3]+b1);
            *(float2*)(C + (size_t)r*N + cb)     = v0;
            *(float2*)(C + (size_t)(r+8)*N + cb) = v1;
        }
    }
}

// ================= k/v projections: x[1024x2048] @ W[2048x8] + b ===========
__global__ __launch_bounds__(128) void kv_gemm(
    const float* __restrict__ x,
    const float* __restrict__ Wk, const float* __restrict__ bk,
    const float* __restrict__ Wv, const float* __restrict__ bv,
    float* __restrict__ kout, float* __restrict__ vout)
{
    __shared__ float xs[D_MODEL];
    const int i = blockIdx.x, tid = threadIdx.x;
    #pragma unroll
    for (int r = 0; r < 4; r++){
        int f = tid + 128*r;
        ((float4*)xs)[f] = ((const float4*)(x + (size_t)i*D_MODEL))[f];
    }
    __syncthreads();
    const int warp = tid >> 5, lane = tid & 31;
    for (int cc = 0; cc < 4; ++cc){
        int col = warp*4 + cc;                 // 0..15: 0-7 -> K, 8-15 -> V
        const float* W = (col < 8) ? Wk : Wv;
        int c = col & 7;
        float acc = 0.f;
        for (int j = lane; j < D_MODEL; j += 32)
            acc = fmaf(xs[j], W[j*8 + c], acc);
        #pragma unroll
        for (int off = 16; off; off >>= 1)
            acc += __shfl_xor_sync(0xffffffffu, acc, off);
        if (lane == 0){
            float b = (col < 8) ? bk[c] : bv[c];
            ((col < 8) ? kout : vout)[i*8 + c] = acc + b;
        }
    }
}

// ================= fused causal MQA attention ==============================
// K,V resident in SMEM as fp16 rows (16B/row, XOR-swizzled -> conflict-free
// LDS.128). One warp handles a (row i, head-pair); score row in 32 regs/lane
// with lane*4 mapping so score stores are STG.128. Warp-uniform 128-wide
// chunk guards (8 per pass) replace 96 per-32 branches. 128-thr CTAs for
// ~3 CTAs/SM. Block b pairs rows i=b and i=1023-b.
#define KH_BYTES (SEQ*16)
#define ATTN_SMEM (2*KH_BYTES + 2*D_MODEL*4)   // 49152 B

static __device__ __forceinline__ unsigned kvswz(unsigned off){
    return off ^ (((off >> 7) & 3u) << 4);
}

__global__ __launch_bounds__(128) void attn_kernel(
    const float* __restrict__ q, const float* __restrict__ k,
    const float* __restrict__ v, float* __restrict__ scores,
    float* __restrict__ y)
{
    extern __shared__ char smc[];
    char* kh = smc;
    char* vh = smc + KH_BYTES;
    float* qsh = (float*)(smc + 2*KH_BYTES);
    const int tid = threadIdx.x;
    const int i1 = blockIdx.x, i2 = (SEQ-1) - blockIdx.x;

    // stage K,V as swizzled half2
    for (int idx = tid; idx < SEQ*4; idx += 128){
        int j = idx >> 2, dp = idx & 3;
        float2 kf2 = *(const float2*)(k + j*8 + dp*2);
        float2 vf2 = *(const float2*)(v + j*8 + dp*2);
        unsigned off = kvswz(j*16 + dp*4);
        *(half2*)(kh + off) = __float22half2_rn(kf2);
        *(half2*)(vh + off) = __float22half2_rn(vf2);
    }
    for (int idx = tid; idx < D_MODEL; idx += 128){
        qsh[idx]           = q[(size_t)i1*D_MODEL + idx];
        qsh[D_MODEL + idx] = q[(size_t)i2*D_MODEL + idx];
    }
    __syncthreads();

    const int warp = tid >> 5, lane = tid & 31;
    const float SCALE = 0.35355339059327373f;   // 1/sqrt(8)
    const float L2E   = 1.4426950408889634f;

    for (int ii = 0; ii < 2; ++ii){
        const int i = ii ? i2 : i1;
        const float* qrow = qsh + ii*D_MODEL;

        for (int g = warp; g < NHEADS/2; g += 4){
            const int h0 = 2*g, h1 = 2*g + 1;
            float qa[8], qb[8];
            #pragma unroll
            for (int d = 0; d < 8; ++d){
                qa[d] = qrow[h0*8+d]*SCALE;
                qb[d] = qrow[h1*8+d]*SCALE;
            }
            float s0[8][4], s1[8][4];
            float m0 = -1e30f, m1 = -1e30f;
            #pragma unroll
            for (int tt = 0; tt < 8; ++tt){
                if (tt*128 <= i){               // warp-uniform guard
                    #pragma unroll
                    for (int jj = 0; jj < 4; ++jj){
                        int j = tt*128 + lane*4 + jj;
                        uint4 kk = *(const uint4*)(kh + kvswz(j*16));
                        float2 k01 = __half22float2(*(half2*)&kk.x);
                        float2 k23 = __half22float2(*(half2*)&kk.y);
                        float2 k45 = __half22float2(*(half2*)&kk.z);
                        float2 k67 = __half22float2(*(half2*)&kk.w);
                        float d0, d1;
                        d0 = qa[0]*k01.x; d1 = qb[0]*k01.x;
                        d0 = fmaf(qa[1], k01.y, d0); d1 = fmaf(qb[1], k01.y, d1);
                        d0 = fmaf(qa[2], k23.x, d0); d1 = fmaf(qb[2], k23.x, d1);
                        d0 = fmaf(qa[3], k23.y, d0); d1 = fmaf(qb[3], k23.y, d1);
                        d0 = fmaf(qa[4], k45.x, d0); d1 = fmaf(qb[4], k45.x, d1);
                        d0 = fmaf(qa[5], k45.y, d0); d1 = fmaf(qb[5], k45.y, d1);
                        d0 = fmaf(qa[6], k67.x, d0); d1 = fmaf(qb[6], k67.x, d1);
                        d0 = fmaf(qa[7], k67.y, d0); d1 = fmaf(qb[7], k67.y, d1);
                        bool val = (j <= i);
                        s0[tt][jj] = val ? d0 : -1e30f;
                        s1[tt][jj] = val ? d1 : -1e30f;
                        m0 = fmaxf(m0, s0[tt][jj]); m1 = fmaxf(m1, s1[tt][jj]);
                    }
                }
            }
            #pragma unroll
            for (int off = 16; off; off >>= 1){
                m0 = fmaxf(m0, __shfl_xor_sync(~0u, m0, off));
                m1 = fmaxf(m1, __shfl_xor_sync(~0u, m1, off));
            }
            float l0 = 0.f, l1 = 0.f;
            #pragma unroll
            for (int tt = 0; tt < 8; ++tt){
                if (tt*128 <= i){
                    #pragma unroll
                    for (int jj = 0; jj < 4; ++jj){
                        float e0 = exp2f((s0[tt][jj]-m0)*L2E);
                        float e1 = exp2f((s1[tt][jj]-m1)*L2E);
                        s0[tt][jj] = e0; s1[tt][jj] = e1;
                        l0 += e0; l1 += e1;
                    }
                }
            }
            #pragma unroll
            for (int off = 16; off; off >>= 1){
                l0 += __shfl_xor_sync(~0u, l0, off);
                l1 += __shfl_xor_sync(~0u, l1, off);
            }
            const float r0 = 1.f/l0, r1 = 1.f/l1;
            float a0[8], a1[8];
            #pragma unroll
            for (int d = 0; d < 8; ++d){ a0[d] = 0.f; a1[d] = 0.f; }
            const size_t row0 = ((size_t)h0*SEQ + i)*SEQ;
            const size_t row1 = ((size_t)h1*SEQ + i)*SEQ;
            #pragma unroll
            for (int tt = 0; tt < 8; ++tt){
                const int jbase = tt*128 + lane*4;
                if (tt*128 <= i){
                    float p0[4], p1[4];
                    #pragma unroll
                    for (int jj = 0; jj < 4; ++jj){
                        p0[jj] = s0[tt][jj]*r0;   // masked entries: exp->0, so p=0
                        p1[jj] = s1[tt][jj]*r1;
                    }
                    if (scores){
                        *(float4*)(scores + row0 + jbase) =
                            make_float4(p0[0],p0[1],p0[2],p0[3]);
                        *(float4*)(scores + row1 + jbase) =
                            make_float4(p1[0],p1[1],p1[2],p1[3]);
                    }
                    #pragma unroll
                    for (int jj = 0; jj < 4; ++jj){
                        int j = jbase + jj;
                        uint4 vv = *(const uint4*)(vh + kvswz(j*16));
                        float2 v01 = __half22float2(*(half2*)&vv.x);
                        float2 v23 = __half22float2(*(half2*)&vv.y);
                        float2 v45 = __half22float2(*(half2*)&vv.z);
                        float2 v67 = __half22float2(*(half2*)&vv.w);
                        a0[0]=fmaf(p0[jj],v01.x,a0[0]); a1[0]=fmaf(p1[jj],v01.x,a1[0]);
                        a0[1]=fmaf(p0[jj],v01.y,a0[1]); a1[1]=fmaf(p1[jj],v01.y,a1[1]);
                        a0[2]=fmaf(p0[jj],v23.x,a0[2]); a1[2]=fmaf(p1[jj],v23.x,a1[2]);
                        a0[3]=fmaf(p0[jj],v23.y,a0[3]); a1[3]=fmaf(p1[jj],v23.y,a1[3]);
                        a0[4]=fmaf(p0[jj],v45.x,a0[4]); a1[4]=fmaf(p1[jj],v45.x,a1[4]);
                        a0[5]=fmaf(p0[jj],v45.y,a0[5]); a1[5]=fmaf(p1[jj],v45.y,a1[5]);
                        a0[6]=fmaf(p0[jj],v67.x,a0[6]); a1[6]=fmaf(p1[jj],v67.x,a1[6]);
                        a0[7]=fmaf(p0[jj],v67.y,a0[7]); a1[7]=fmaf(p1[jj],v67.y,a1[7]);
                    }
                } else if (scores){
                    float4 Z = make_float4(0.f,0.f,0.f,0.f);
                    *(float4*)(scores + row0 + jbase) = Z;
                    *(float4*)(scores + row1 + jbase) = Z;
                }
            }
            #pragma unroll
            for (int d = 0; d < 8; ++d){
                #pragma unroll
                for (int off = 16; off; off >>= 1){
                    a0[d] += __shfl_xor_sync(~0u, a0[d], off);
                    a1[d] += __shfl_xor_sync(~0u, a1[d], off);
                }
            }
            if (lane == 0){
                float* y0 = y + (size_t)i*D_MODEL + h0*8;
                *(float4*)(y0)     = make_float4(a0[0],a0[1],a0[2],a0[3]);
                *(float4*)(y0 + 4) = make_float4(a0[4],a0[5],a0[6],a0[7]);
                float* y1 = y + (size_t)i*D_MODEL + h1*8;
                *(float4*)(y1)     = make_float4(a1[0],a1[1],a1[2],a1[3]);
                *(float4*)(y1 + 4) = make_float4(a1[4],a1[5],a1[6],a1[7]);
            }
        }
    }
}

// ============================ launcher =====================================
extern "C" void kernel_launch(void* const* d_in, const int* in_sizes, int n_in,
                              void* d_out, int out_size)
{
    const float* x  = (const float*)d_in[0];
    // d_in[1] = mask (int32 tril) -- causal structure is known, unused
    const float* Wq = (const float*)d_in[2];
    const float* bq = (const float*)d_in[3];
    const float* Wk = (const float*)d_in[4];
    const float* bk = (const float*)d_in[5];
    const float* Wv = (const float*)d_in[6];
    const float* bv = (const float*)d_in[7];
    const float* Wo = (const float*)d_in[8];
    const float* bo = (const float*)d_in[9];

    float* out = (float*)d_out;
    float* scores = (out_size > OUT_ELEMS) ? (out + OUT_ELEMS) : nullptr;

    float *qg, *yg, *kg, *vg;
    cudaGetSymbolAddress((void**)&qg, g_q);
    cudaGetSymbolAddress((void**)&yg, g_y);
    cudaGetSymbolAddress((void**)&kg, g_k);
    cudaGetSymbolAddress((void**)&vg, g_v);

    cudaFuncSetAttribute(gemm3tf32,
        cudaFuncAttributeMaxDynamicSharedMemorySize, GEMM_SMEM);
    cudaFuncSetAttribute(attn_kernel,
        cudaFuncAttributeMaxDynamicSharedMemorySize, ATTN_SMEM);

    // q = x @ Wq + bq
    gemm3tf32<<<dim3(D_MODEL/GBN, SEQ/GBM), 256, GEMM_SMEM>>>(x, Wq, bq, qg, SEQ, D_MODEL, D_MODEL);
    // k, v projections
    kv_gemm<<<SEQ, 128>>>(x, Wk, bk, Wv, bv, kg, vg);
    // fused attention: probs -> scores output, context -> g_y
    attn_kernel<<<SEQ/2, 128, ATTN_SMEM>>>(qg, kg, vg, scores, yg);
    // out = y @ Wo + bo
    gemm3tf32<<<dim3(D_MODEL/GBN, SEQ/GBM), 256, GEMM_SMEM>>>(yg, Wo, bo, out, SEQ, D_MODEL, D_MODEL);
}